// round 2
// baseline (speedup 1.0000x reference)
#include <cuda_runtime.h>

#define B 256
#define NFULL 100
#define R 80
#define D 768
#define D4 (D / 4)          // 192 float4 per row
#define THRESH 0.5f

// Scratch (allocation-free rule: __device__ globals)
__device__ int g_perm[B * R];
__device__ int g_counts[B];

// ---------------------------------------------------------------------------
// Kernel 1: per-batch-row metadata.
// Computes binary, stable compaction perm, counts, rr_mod (+zero-row fixup),
// labels passthrough, text_mask, img_mask.
// ---------------------------------------------------------------------------
__global__ void meta_kernel(const float* __restrict__ rr_in,      // (B,100)
                            const float* __restrict__ labels_in,  // (B,100)
                            float* __restrict__ text_mask,        // (B,81)
                            float* __restrict__ img_mask,         // (B,81)
                            float* __restrict__ rr_mod_out,       // (B,80)
                            float* __restrict__ labels_out)       // (B,80)
{
    int b = blockIdx.x;
    int t = threadIdx.x;  // 128 threads

    __shared__ float s_rr[R];
    __shared__ int   s_bin[R];
    __shared__ int   s_pos[R];
    __shared__ int   s_count;
    __shared__ int   s_any_ge;  // any rr >= 0.5 -> row is NOT a zero-row

    if (t < R) {
        float r = rr_in[b * NFULL + t];
        s_rr[t]  = r;
        s_bin[t] = (r > THRESH) ? 1 : 0;
    }
    __syncthreads();

    if (t == 0) {
        int c = 0;
        int any_ge = 0;
        #pragma unroll 8
        for (int i = 0; i < R; i++) {
            s_pos[i] = c;
            c += s_bin[i];
            if (s_rr[i] >= THRESH) any_ge = 1;
        }
        s_count  = c;
        s_any_ge = any_ge;
        g_counts[b] = c;
    }
    __syncthreads();

    int cnt = s_count;

    if (t < R) {
        // stable compaction permutation
        if (s_bin[t]) g_perm[b * R + s_pos[t]] = t;

        // rr_mod: zero entries strictly below threshold; rr==0.5 survives
        float r  = s_rr[t];
        float rm = (r < THRESH) ? 0.0f : r;
        // zero-row fixup: if the whole row of rr_mod is zero, slot 0 -> 1.0
        if (t == 0 && !s_any_ge) rm = 1.0f;
        rr_mod_out[b * R + t] = rm;

        // labels passthrough
        labels_out[b * R + t] = labels_in[b * NFULL + t];
    }

    if (t <= R) {  // 81 positions
        float tm = (t <= cnt) ? 1.0f : 0.0f;
        text_mask[b * (R + 1) + t] = tm;
        img_mask [b * (R + 1) + t] = (b == B - 1) ? tm : 1.0f;
    }
}

// ---------------------------------------------------------------------------
// Kernel 2: the heavy gather. One block per (slot j, batch b); 192 threads,
// one float4 each, for both vis and txt. Slots >= counts[b] get zeros
// (d_out is poisoned, so explicit zero writes are mandatory).
// ---------------------------------------------------------------------------
__global__ void copy_kernel(const float4* __restrict__ vis,       // (B,100,192)
                            const float4* __restrict__ txt,       // (B,100,192)
                            float4* __restrict__ vis_out,         // (B,80,192)
                            float4* __restrict__ txt_out)         // (B,80,192)
{
    int j = blockIdx.x;   // 0..79
    int b = blockIdx.y;   // 0..255
    int t = threadIdx.x;  // 0..191

    int cnt = g_counts[b];
    long out_off = ((long)(b * R + j)) * D4 + t;

    if (j < cnt) {
        int src = g_perm[b * R + j];
        long in_off = ((long)(b * NFULL + src)) * D4 + t;
        vis_out[out_off] = vis[in_off];
        txt_out[out_off] = txt[in_off];
    } else {
        float4 z = make_float4(0.0f, 0.0f, 0.0f, 0.0f);
        vis_out[out_off] = z;
        txt_out[out_off] = z;
    }
}

// ---------------------------------------------------------------------------
// Launch
// Inputs (metadata order):
//   0: mean_pooling_vec (unused)   1: merge_text_vec (unused)
//   2: retrieved_visual_feature_embedding_cls (B,100,1,768)
//   3: retrieved_textual_feature_embedding   (B,100,1,768)
//   4: retrieved_label_list (B,100)          5: RRCP (B,100)
// Output (concatenated f32):
//   vis_packed (B,80,768) | txt_packed (B,80,768) | text_mask (B,81)
//   | img_mask (B,81) | rr_mod (B,80) | labels (B,80)
// ---------------------------------------------------------------------------
extern "C" void kernel_launch(void* const* d_in, const int* in_sizes, int n_in,
                              void* d_out, int out_size)
{
    const float* vis    = (const float*)d_in[2];
    const float* txt    = (const float*)d_in[3];
    const float* labels = (const float*)d_in[4];
    const float* rr     = (const float*)d_in[5];

    float* out = (float*)d_out;
    const long VIS_SZ = (long)B * R * D;        // 15,728,640
    const long MASK_SZ = (long)B * (R + 1);     // 20,736
    const long ROW_SZ  = (long)B * R;           // 20,480

    float* vis_out   = out;
    float* txt_out   = out + VIS_SZ;
    float* text_mask = out + 2 * VIS_SZ;
    float* img_mask  = text_mask + MASK_SZ;
    float* rr_mod    = img_mask + MASK_SZ;
    float* labels_o  = rr_mod + ROW_SZ;

    meta_kernel<<<B, 128>>>(rr, labels, text_mask, img_mask, rr_mod, labels_o);

    dim3 grid(R, B);
    copy_kernel<<<grid, D4>>>((const float4*)vis, (const float4*)txt,
                              (float4*)vis_out, (float4*)txt_out);
}

// round 5
// speedup vs baseline: 1.1319x; 1.1319x over previous
#include <cuda_runtime.h>

#define B 256
#define NFULL 100
#define R 80
#define D4 192            // 768 / 4 floats per float4 row
#define THRESH 0.5f

// ---------------------------------------------------------------------------
// Single fused kernel. Grid (R, B), 192 threads.
// Each block (j, b):
//   - recomputes the batch-b compaction info from the RRCP row (L2-resident)
//     via warp ballots; thread 0 extracts src = index of j-th kept element.
//   - blocks with j==0 additionally emit the metadata outputs.
//   - all threads stream one float4 of vis + one of txt (gather or zero-fill).
// ---------------------------------------------------------------------------
__global__ void fused_kernel(const float4* __restrict__ vis,      // (B,100,192)
                             const float4* __restrict__ txt,      // (B,100,192)
                             const float*  __restrict__ rr_in,    // (B,100)
                             const float*  __restrict__ labels_in,// (B,100)
                             float4* __restrict__ vis_out,        // (B,80,192)
                             float4* __restrict__ txt_out,        // (B,80,192)
                             float*  __restrict__ text_mask,      // (B,81)
                             float*  __restrict__ img_mask,       // (B,81)
                             float*  __restrict__ rr_mod,         // (B,80)
                             float*  __restrict__ labels_out)     // (B,80)
{
    const int j = blockIdx.x;   // 0..79   slot
    const int b = blockIdx.y;   // 0..255  batch
    const int t = threadIdx.x;  // 0..191

    __shared__ unsigned s_m[3];   // bin masks  (rr >  0.5)
    __shared__ unsigned s_mg[3];  // ge  masks  (rr >= 0.5)
    __shared__ int      s_cnt, s_src, s_anyge;
    __shared__ float    s_rr[R];

    float r  = 0.0f;
    bool bin = false, ge = false;
    if (t < R) {
        r   = rr_in[b * NFULL + t];
        bin = (r > THRESH);
        ge  = (r >= THRESH);
    }
    unsigned m  = __ballot_sync(0xffffffffu, bin);
    unsigned mg = __ballot_sync(0xffffffffu, ge);
    int w = t >> 5;
    if ((t & 31) == 0 && w < 3) { s_m[w] = m; s_mg[w] = mg; }
    if (j == 0 && t < R) s_rr[t] = r;
    __syncthreads();

    if (t == 0) {
        unsigned m0 = s_m[0], m1 = s_m[1], m2 = s_m[2];
        int c0 = __popc(m0), c1 = __popc(m1), c2 = __popc(m2);
        int cnt = c0 + c1 + c2;
        s_cnt = cnt;
        int src = -1;
        if (j < cnt) {
            int rem = j;
            if (rem < c0)            src = (int)__fns(m0, 0, rem + 1);
            else {
                rem -= c0;
                if (rem < c1)        src = 32 + (int)__fns(m1, 0, rem + 1);
                else { rem -= c1;    src = 64 + (int)__fns(m2, 0, rem + 1); }
            }
        }
        s_src   = src;
        s_anyge = ((s_mg[0] | s_mg[1] | s_mg[2]) != 0);
    }
    __syncthreads();

    const int cnt = s_cnt;

    // Metadata outputs: only one block per batch does these (tiny traffic).
    if (j == 0) {
        if (t < R) {
            float rv = s_rr[t];
            float rm = (rv < THRESH) ? 0.0f : rv;      // rr==0.5 survives
            if (t == 0 && !s_anyge) rm = 1.0f;         // zero-row fixup
            rr_mod[b * R + t]     = rm;
            labels_out[b * R + t] = labels_in[b * NFULL + t];
        }
        if (t <= R) {  // 81 entries
            float tm = (t <= cnt) ? 1.0f : 0.0f;
            text_mask[b * (R + 1) + t] = tm;
            img_mask [b * (R + 1) + t] = (b == B - 1) ? tm : 1.0f;
        }
    }

    // The heavy streaming copy: 2 x 16 B per thread, fully coalesced.
    const long out_off = ((long)(b * R + j)) * D4 + t;
    if (j < cnt) {
        const long in_off = ((long)(b * NFULL + s_src)) * D4 + t;
        float4 v = __ldcs(vis + in_off);
        float4 x = __ldcs(txt + in_off);
        __stcs(vis_out + out_off, v);
        __stcs(txt_out + out_off, x);
    } else {
        float4 z = make_float4(0.0f, 0.0f, 0.0f, 0.0f);
        __stcs(vis_out + out_off, z);
        __stcs(txt_out + out_off, z);
    }
}

// ---------------------------------------------------------------------------
// Inputs (metadata order):
//   0: mean_pooling_vec (unused)   1: merge_text_vec (unused)
//   2: retrieved_visual_feature_embedding_cls (B,100,1,768)
//   3: retrieved_textual_feature_embedding   (B,100,1,768)
//   4: retrieved_label_list (B,100)          5: RRCP (B,100)
// Output (concatenated f32):
//   vis_packed (B,80,768) | txt_packed (B,80,768) | text_mask (B,81)
//   | img_mask (B,81) | rr_mod (B,80) | labels (B,80)
// ---------------------------------------------------------------------------
extern "C" void kernel_launch(void* const* d_in, const int* in_sizes, int n_in,
                              void* d_out, int out_size)
{
    const float* vis    = (const float*)d_in[2];
    const float* txt    = (const float*)d_in[3];
    const float* labels = (const float*)d_in[4];
    const float* rr     = (const float*)d_in[5];

    float* out = (float*)d_out;
    const long VIS_SZ  = (long)B * R * 768;     // 15,728,640
    const long MASK_SZ = (long)B * (R + 1);     // 20,736
    const long ROW_SZ  = (long)B * R;           // 20,480

    float* vis_out   = out;
    float* txt_out   = out + VIS_SZ;
    float* text_mask = out + 2 * VIS_SZ;
    float* img_mask  = text_mask + MASK_SZ;
    float* rr_mod    = img_mask + MASK_SZ;
    float* labels_o  = rr_mod + ROW_SZ;

    dim3 grid(R, B);
    fused_kernel<<<grid, D4>>>((const float4*)vis, (const float4*)txt,
                               rr, labels,
                               (float4*)vis_out, (float4*)txt_out,
                               text_mask, img_mask, rr_mod, labels_o);
}